// round 13
// baseline (speedup 1.0000x reference)
#include <cuda_runtime.h>
#include <math.h>

typedef unsigned long long u64;

#define B_  2
#define S_  2048
#define D_  1024
#define H_  16
#define HD_ 64
#define M_  (B_ * S_)   // 4096

// Scratch (device globals; allocation is forbidden).
__device__ float g_q[B_ * H_ * S_ * HD_];
__device__ float g_k[B_ * H_ * S_ * HD_];
__device__ float g_v[B_ * H_ * S_ * HD_];
__device__ float g_ctx[B_ * S_ * D_];

// ---- packed fp32x2 helpers (FFMA2 path: only reachable via PTX) -----------
__device__ __forceinline__ void ffma2(u64& d, u64 a, u64 b) {
    asm("fma.rn.f32x2 %0, %1, %2, %0;" : "+l"(d) : "l"(a), "l"(b));
}
__device__ __forceinline__ u64 swap2(u64 v) {   // swap 32-bit halves
    u64 r;
    asm("{\n\t.reg .b32 lo, hi;\n\tmov.b64 {lo, hi}, %1;\n\tmov.b64 %0, {hi, lo};\n\t}"
        : "=l"(r) : "l"(v));
    return r;
}
__device__ __forceinline__ float2 unpack2(u64 v) {
    float2 r; asm("mov.b64 {%0, %1}, %2;" : "=f"(r.x), "=f"(r.y) : "l"(v)); return r;
}

// ---------------------------------------------------------------------------
// Tiled SGEMM, FFMA2 *diagonal-pair* scheme (no splat): both operands are
// natural adjacent pairs; each 2x2 C-subtile is held as diag + anti-diag
// packed accumulators:
//   accD[i][j] += ap_i * bp_j        -> (C[2i][2j],   C[2i+1][2j+1])
//   accX[i][j] += ap_i * swap(bp_j)  -> (C[2i][2j+1], C[2i+1][2j])
// Per k: 4 LDS.128 (same smem bytes as scalar) + 32 FFMA2 (half the instrs).
// BM=BN=128, BK=16, 256 threads, 8x8 tile/thread. R11 lesson: splatted
// operands doubled smem traffic -> L1 pipe 77.5% was the binding resource.
// ---------------------------------------------------------------------------
template <bool SPLIT, bool QKV>
__global__ __launch_bounds__(256, 2) void gemm_kernel(
    const float* __restrict__ A,
    const float* __restrict__ Wa, const float* __restrict__ ba, float* __restrict__ oa,
    const float* __restrict__ Wb, const float* __restrict__ bb, float* __restrict__ ob,
    const float* __restrict__ Wc, const float* __restrict__ bc, float* __restrict__ oc)
{
    const float* W = Wa; const float* bias = ba; float* out = oa;
    if (QKV) {
        int z = blockIdx.z;
        if (z == 1) { W = Wb; bias = bb; out = ob; }
        if (z == 2) { W = Wc; bias = bc; out = oc; }
    }

    __shared__ float As[16][132];   // A tile transposed: As[k][m] (pitch 132)
    __shared__ float Bs[16][128];   // W tile: Bs[k][n]

    const int t    = threadIdx.x;
    const int tx   = t & 15;
    const int ty   = t >> 4;
    const int n0   = blockIdx.x * 128;
    const int row0 = blockIdx.y * 128;

    u64 accD[4][4], accX[4][4];
#pragma unroll
    for (int i = 0; i < 4; i++)
#pragma unroll
        for (int j = 0; j < 4; j++) { accD[i][j] = 0ull; accX[i][j] = 0ull; }

    for (int k0 = 0; k0 < D_; k0 += 16) {
#pragma unroll
        for (int l = 0; l < 2; l++) {
            int idx = t + l * 256;
            int ar = idx >> 2, ac4 = idx & 3;
            float4 a4 = *(const float4*)&A[(size_t)(row0 + ar) * D_ + k0 + ac4 * 4];
            As[ac4 * 4 + 0][ar] = a4.x;
            As[ac4 * 4 + 1][ar] = a4.y;
            As[ac4 * 4 + 2][ar] = a4.z;
            As[ac4 * 4 + 3][ar] = a4.w;
            int kr = idx >> 5, bc4 = idx & 31;
            *(float4*)&Bs[kr][bc4 * 4] =
                *(const float4*)&W[(size_t)(k0 + kr) * D_ + n0 + bc4 * 4];
        }
        __syncthreads();

#pragma unroll
        for (int k = 0; k < 16; k++) {
            ulonglong2 a01 = *(const ulonglong2*)&As[k][ty * 8];
            ulonglong2 a23 = *(const ulonglong2*)&As[k][ty * 8 + 4];
            ulonglong2 b01 = *(const ulonglong2*)&Bs[k][tx * 8];
            ulonglong2 b23 = *(const ulonglong2*)&Bs[k][tx * 8 + 4];
            u64 ap[4] = { a01.x, a01.y, a23.x, a23.y };
            u64 bp[4] = { b01.x, b01.y, b23.x, b23.y };
            u64 bs[4] = { swap2(bp[0]), swap2(bp[1]), swap2(bp[2]), swap2(bp[3]) };
#pragma unroll
            for (int i = 0; i < 4; i++)
#pragma unroll
                for (int j = 0; j < 4; j++) {
                    ffma2(accD[i][j], ap[i], bp[j]);
                    ffma2(accX[i][j], ap[i], bs[j]);
                }
        }
        __syncthreads();
    }

    // Epilogue: unscramble diag/anti-diag, add bias, store float2 per row.
#pragma unroll
    for (int i = 0; i < 4; i++) {
        int row_e = row0 + ty * 8 + 2 * i;
#pragma unroll
        for (int j = 0; j < 4; j++) {
            int col = n0 + tx * 8 + 2 * j;
            float2 de = unpack2(accD[i][j]);   // (C[re][c],   C[ro][c+1])
            float2 xe = unpack2(accX[i][j]);   // (C[re][c+1], C[ro][c])
            float b0 = bias[col], b1 = bias[col + 1];
            float2 ve = make_float2(de.x + b0, xe.x + b1);   // even row
            float2 vo = make_float2(xe.y + b0, de.y + b1);   // odd row
            if (SPLIT) {
                int h = col >> 6, hd = col & 63;
                int be = row_e >> 11, se = row_e & (S_ - 1);
                int bo2 = (row_e + 1) >> 11, so = (row_e + 1) & (S_ - 1);
                *(float2*)&out[(((size_t)(be * H_ + h)) * S_ + se) * HD_ + hd] = ve;
                *(float2*)&out[(((size_t)(bo2 * H_ + h)) * S_ + so) * HD_ + hd] = vo;
            } else {
                *(float2*)&out[(size_t)row_e * D_ + col] = ve;
                *(float2*)&out[(size_t)(row_e + 1) * D_ + col] = vo;
            }
        }
    }
}

// ---------------------------------------------------------------------------
// Flash-attention: REVERTED to the measured R1 scalar version (939us, fma
// 59.9%). FFMA2+splat attn regressed twice (R7/R11: splat doubled smem
// traffic). Diag-pair port of attn is next round once GEMM confirms.
// Block = 64 queries of one (b,h). 256 threads as 16x16, 4x4 micro-tile.
// K transposed + XOR-swizzled; online softmax; P reuses K buffer.
// Dynamic smem: Qs[64][68] + Vs[64][68] + KP[64*68] = 52224 bytes.
// ---------------------------------------------------------------------------
__global__ __launch_bounds__(256) void attn_kernel()
{
    extern __shared__ float smx[];
    float* Qs = smx;                 // [64][68]
    float* Vs = smx + 64 * 68;       // [64][68]
    float* KP = smx + 2 * 64 * 68;   // Kt [64][64] swizzled, then Ps [64][68]

    const int t  = threadIdx.x;
    const int tx = t & 15;
    const int ty = t >> 4;
    const int q0 = blockIdx.x * 64;
    const int bh = blockIdx.y;       // b*H + h
    const size_t base = (size_t)bh * S_ * HD_;
    const float* Qg = g_q + base;
    const float* Kg = g_k + base;
    const float* Vg = g_v + base;

    // Q tile (pre-scaled by 1/sqrt(HD) = 0.125)
#pragma unroll
    for (int l = 0; l < 4; l++) {
        int idx = t + l * 256;       // 1024 float4s
        int r = idx >> 4, c4 = idx & 15;
        float4 v = *(const float4*)&Qg[(size_t)(q0 + r) * HD_ + c4 * 4];
        v.x *= 0.125f; v.y *= 0.125f; v.z *= 0.125f; v.w *= 0.125f;
        *(float4*)&Qs[r * 68 + c4 * 4] = v;
    }

    float m_i[4], l_i[4], o[4][4];
#pragma unroll
    for (int i = 0; i < 4; i++) {
        m_i[i] = -1e30f;
        l_i[i] = 0.f;
#pragma unroll
        for (int j = 0; j < 4; j++) o[i][j] = 0.f;
    }
    __syncthreads();

    for (int kt = 0; kt < S_ / 64; kt++) {
        const int k0 = kt * 64;
        // Load K (transposed + swizzled) and V (row-major)
#pragma unroll
        for (int l = 0; l < 4; l++) {
            int idx = t + l * 256;
            int r = idx >> 4, c4 = idx & 15;
            float4 kv = *(const float4*)&Kg[(size_t)(k0 + r) * HD_ + c4 * 4];
            int pos = (((r >> 2) ^ c4) << 2) + (r & 3);   // swizzle on key-group
            KP[(c4 * 4 + 0) * 64 + pos] = kv.x;
            KP[(c4 * 4 + 1) * 64 + pos] = kv.y;
            KP[(c4 * 4 + 2) * 64 + pos] = kv.z;
            KP[(c4 * 4 + 3) * 64 + pos] = kv.w;
            *(float4*)&Vs[r * 68 + c4 * 4] =
                *(const float4*)&Vg[(size_t)(k0 + r) * HD_ + c4 * 4];
        }
        __syncthreads();

        // S = Q @ K^T   (thread: rows ty*4+i, keys tx*4+j)
        float s[4][4];
#pragma unroll
        for (int i = 0; i < 4; i++)
#pragma unroll
            for (int j = 0; j < 4; j++) s[i][j] = 0.f;

#pragma unroll
        for (int dd = 0; dd < 64; dd += 4) {
            int sw = ((tx ^ (dd >> 2)) << 2);
            float4 b0 = *(const float4*)&KP[(dd + 0) * 64 + sw];
            float4 b1 = *(const float4*)&KP[(dd + 1) * 64 + sw];
            float4 b2 = *(const float4*)&KP[(dd + 2) * 64 + sw];
            float4 b3 = *(const float4*)&KP[(dd + 3) * 64 + sw];
#pragma unroll
            for (int i = 0; i < 4; i++) {
                float4 a = *(const float4*)&Qs[(ty * 4 + i) * 68 + dd];
                s[i][0] += a.x * b0.x + a.y * b1.x + a.z * b2.x + a.w * b3.x;
                s[i][1] += a.x * b0.y + a.y * b1.y + a.z * b2.y + a.w * b3.y;
                s[i][2] += a.x * b0.z + a.y * b1.z + a.z * b2.z + a.w * b3.z;
                s[i][3] += a.x * b0.w + a.y * b1.w + a.z * b2.w + a.w * b3.w;
            }
        }
        __syncthreads();   // all reads of KP-as-Kt done before P overwrites it

        // Online softmax. Row group = 16 lanes (tx); shfl width-16 reductions.
#pragma unroll
        for (int i = 0; i < 4; i++) {
            float mx = fmaxf(fmaxf(s[i][0], s[i][1]), fmaxf(s[i][2], s[i][3]));
            mx = fmaxf(mx, __shfl_xor_sync(0xffffffffu, mx, 1));
            mx = fmaxf(mx, __shfl_xor_sync(0xffffffffu, mx, 2));
            mx = fmaxf(mx, __shfl_xor_sync(0xffffffffu, mx, 4));
            mx = fmaxf(mx, __shfl_xor_sync(0xffffffffu, mx, 8));
            float mnew = fmaxf(m_i[i], mx);
            float corr = __expf(m_i[i] - mnew);
            float rs = 0.f;
#pragma unroll
            for (int j = 0; j < 4; j++) {
                s[i][j] = __expf(s[i][j] - mnew);
                rs += s[i][j];
            }
            rs += __shfl_xor_sync(0xffffffffu, rs, 1);
            rs += __shfl_xor_sync(0xffffffffu, rs, 2);
            rs += __shfl_xor_sync(0xffffffffu, rs, 4);
            rs += __shfl_xor_sync(0xffffffffu, rs, 8);
            l_i[i] = l_i[i] * corr + rs;
            m_i[i] = mnew;
#pragma unroll
            for (int j = 0; j < 4; j++) o[i][j] *= corr;
        }

        // P -> smem (reuse KP, pitch 68)
        float* Ps = KP;
#pragma unroll
        for (int i = 0; i < 4; i++)
            *(float4*)&Ps[(ty * 4 + i) * 68 + tx * 4] =
                make_float4(s[i][0], s[i][1], s[i][2], s[i][3]);
        __syncthreads();

        // O += P @ V   (thread: rows ty*4+i, dims tx*4+j)
#pragma unroll
        for (int kk = 0; kk < 64; kk += 4) {
            float4 v0 = *(const float4*)&Vs[(kk + 0) * 68 + tx * 4];
            float4 v1 = *(const float4*)&Vs[(kk + 1) * 68 + tx * 4];
            float4 v2 = *(const float4*)&Vs[(kk + 2) * 68 + tx * 4];
            float4 v3 = *(const float4*)&Vs[(kk + 3) * 68 + tx * 4];
#pragma unroll
            for (int i = 0; i < 4; i++) {
                float4 p = *(const float4*)&Ps[(ty * 4 + i) * 68 + kk];
                o[i][0] += p.x * v0.x + p.y * v1.x + p.z * v2.x + p.w * v3.x;
                o[i][1] += p.x * v0.y + p.y * v1.y + p.z * v2.y + p.w * v3.y;
                o[i][2] += p.x * v0.z + p.y * v1.z + p.z * v2.z + p.w * v3.z;
                o[i][3] += p.x * v0.w + p.y * v1.w + p.z * v2.w + p.w * v3.w;
            }
        }
        __syncthreads();   // before next tile overwrites KP/Vs
    }

    // ctx[b, s, h*64 + d] = O / l
    const int b = bh >> 4;
    const int h = bh & 15;
#pragma unroll
    for (int i = 0; i < 4; i++) {
        float inv = 1.f / l_i[i];
        int srow = q0 + ty * 4 + i;
        *(float4*)&g_ctx[((size_t)(b * S_ + srow)) * D_ + h * HD_ + tx * 4] =
            make_float4(o[i][0] * inv, o[i][1] * inv, o[i][2] * inv, o[i][3] * inv);
    }
}

// ---------------------------------------------------------------------------

extern "C" void kernel_launch(void* const* d_in, const int* in_sizes, int n_in,
                              void* d_out, int out_size)
{
    const float* x  = (const float*)d_in[0];
    const float* Wq = (const float*)d_in[1];
    const float* bq = (const float*)d_in[2];
    const float* Wk = (const float*)d_in[3];
    const float* bk = (const float*)d_in[4];
    const float* Wv = (const float*)d_in[5];
    const float* bv = (const float*)d_in[6];
    const float* Wo = (const float*)d_in[7];
    const float* bo = (const float*)d_in[8];
    float* out = (float*)d_out;

    float *qp, *kp, *vp, *cp;
    cudaGetSymbolAddress((void**)&qp, g_q);
    cudaGetSymbolAddress((void**)&kp, g_k);
    cudaGetSymbolAddress((void**)&vp, g_v);
    cudaGetSymbolAddress((void**)&cp, g_ctx);

    const int ATTN_SMEM = 3 * 64 * 68 * (int)sizeof(float);   // 52224 B
    cudaFuncSetAttribute(attn_kernel,
                         cudaFuncAttributeMaxDynamicSharedMemorySize, ATTN_SMEM);

    dim3 gg(D_ / 128, M_ / 128);   // (8, 32)

    // Fused Q/K/V projection: z selects weight set
    gemm_kernel<true, true><<<dim3(8, 32, 3), 256>>>(
        x, Wq, bq, qp, Wk, bk, kp, Wv, bv, vp);

    attn_kernel<<<dim3(S_ / 64, B_ * H_), 256, ATTN_SMEM>>>();

    gemm_kernel<false, false><<<gg, 256>>>(
        cp, Wo, bo, out, nullptr, nullptr, nullptr, nullptr, nullptr, nullptr);
}